// round 9
// baseline (speedup 1.0000x reference)
#include <cuda_runtime.h>
#include <math.h>

#define Bn 65536
#define NP 2080  // 64*65/2 pairs i<=j

// ---------- device scratch ----------
__device__ float g_cosd[64], g_Finv[4096], g_metric[4096], g_Wf[4096], g_bf[64];
__device__ float g_Dsym[NP * 64];
__device__ unsigned char g_pi[NP], g_pj[NP];
__device__ float g_WqT[4096], g_WkT[4096], g_WvT[4096], g_WoT[4096], g_WuT[4096], g_WsT[4096];
__device__ float g_KT[768 * 64];
__device__ double g_aug[64 * 128];

// ---------- packed f32x2 ----------
typedef unsigned long long u64;
__device__ __forceinline__ u64 pk2(float lo, float hi) {
    u64 r; asm("mov.b64 %0, {%1, %2};" : "=l"(r) : "f"(lo), "f"(hi)); return r;
}
__device__ __forceinline__ void upk2(u64 v, float& lo, float& hi) {
    asm("mov.b64 {%0, %1}, %2;" : "=f"(lo), "=f"(hi) : "l"(v));
}
__device__ __forceinline__ u64 ffma2(u64 a, u64 b, u64 c) {
    u64 d; asm("fma.rn.f32x2 %0, %1, %2, %3;" : "=l"(d) : "l"(a), "l"(b), "l"(c)); return d;
}
// acc[o/2] += xsh[i*256+tid] * W[i*64+o], o=0..63
__device__ __forceinline__ void gemv64(const float* xsh, const float* W, int tid, u64 acc[32]) {
#pragma unroll 4
    for (int i = 0; i < 64; i++) {
        float x = xsh[i * 256 + tid];
        u64 xv = pk2(x, x);
        const ulonglong2* row = (const ulonglong2*)(W + i * 64);
#pragma unroll
        for (int q = 0; q < 16; q++) {
            ulonglong2 w = row[q];
            acc[2 * q] = ffma2(xv, w.x, acc[2 * q]);
            acc[2 * q + 1] = ffma2(xv, w.y, acc[2 * q + 1]);
        }
    }
}
// 8 outputs: cols base..base+7
__device__ __forceinline__ void gemv8(const float* xsh, const float* W, int base, int tid, u64 acc[4]) {
#pragma unroll 4
    for (int i = 0; i < 64; i++) {
        float x = xsh[i * 256 + tid];
        u64 xv = pk2(x, x);
        const ulonglong2* row = (const ulonglong2*)(W + i * 64 + base);
        ulonglong2 w0 = row[0], w1 = row[1];
        acc[0] = ffma2(xv, w0.x, acc[0]); acc[1] = ffma2(xv, w0.y, acc[1]);
        acc[2] = ffma2(xv, w1.x, acc[2]); acc[3] = ffma2(xv, w1.y, acc[3]);
    }
}

__device__ __forceinline__ float fast_sigmoid(float x) { return 1.0f / (1.0f + __expf(-x)); }
__device__ __forceinline__ float fast_tanh(float x) {
    x = fminf(15.0f, fmaxf(-15.0f, x));
    float t = __expf(2.0f * x);
    return (t - 1.0f) / (t + 1.0f);
}

// ============ K0a: single-CTA precompute ============
__global__ void k0a(const float* __restrict__ phase, const float* __restrict__ q_w,
                    const float* __restrict__ k_w, const float* __restrict__ v_w,
                    const float* __restrict__ o_w, const float* __restrict__ update_w,
                    const float* __restrict__ state_w, const float* __restrict__ fisher_m,
                    const float* __restrict__ metric_m, const float* __restrict__ proj_w,
                    const float* __restrict__ proj_b, const float* __restrict__ obj_emb,
                    const float* __restrict__ morphisms, const float* __restrict__ functor_w,
                    const float* __restrict__ out_w, const float* __restrict__ out_b) {
    __shared__ float s_a[4096], s_b[4096], s_fw[64];
    __shared__ double s_f[64], s_bv[2], s_pv;
    __shared__ int s_br[2], s_piv;
    int tid = threadIdx.x;
    if (tid < 64) g_cosd[tid] = cosf(phase[tid >> 3] - phase[tid & 7]);
    for (int idx = tid; idx < 4096; idx += 256) {
        int o = idx >> 6, i = idx & 63;
        g_WqT[i * 64 + o] = q_w[idx];  g_WkT[i * 64 + o] = k_w[idx];
        g_WvT[i * 64 + o] = v_w[idx];  g_WoT[i * 64 + o] = o_w[idx];
        g_WuT[i * 64 + o] = update_w[o * 128 + i];  // h0=0: only first half
        g_WsT[i * 64 + o] = state_w[o * 128 + i];
    }
    for (int idx = tid; idx < 4096; idx += 256) {
        int i = idx >> 6, j = idx & 63;
        float sf = 0.f, sm = 0.f;
        for (int k = 0; k < 64; k++) {
            sf += fisher_m[i * 64 + k] * fisher_m[j * 64 + k];
            sm += metric_m[i * 64 + k] * metric_m[j * 64 + k];
        }
        g_metric[idx] = sm;
        g_aug[i * 128 + j] = (double)sf;
        g_aug[i * 128 + 64 + j] = (j == i) ? 1.0 : 0.0;
    }
    if (tid == 0) {
        int p = 0;
        for (int i = 0; i < 64; i++)
            for (int j = i; j < 64; j++) { g_pi[p] = i; g_pj[p] = j; p++; }
    }
    __syncthreads();
    // Gauss-Jordan (fp64, partial pivot) -> Finv
    for (int col = 0; col < 64; col++) {
        if (tid < 64) {
            double v = (tid >= col) ? fabs(g_aug[tid * 128 + col]) : -1.0;
            int r = tid;
            for (int off = 16; off; off >>= 1) {
                double ov = __shfl_down_sync(0xffffffffu, v, off);
                int orr = __shfl_down_sync(0xffffffffu, r, off);
                if (ov > v) { v = ov; r = orr; }
            }
            if ((tid & 31) == 0) { s_bv[tid >> 5] = v; s_br[tid >> 5] = r; }
        }
        __syncthreads();
        if (tid == 0) s_piv = (s_bv[1] > s_bv[0]) ? s_br[1] : s_br[0];
        __syncthreads();
        int piv = s_piv;
        if (piv != col && tid < 128) {
            double t = g_aug[piv * 128 + tid];
            g_aug[piv * 128 + tid] = g_aug[col * 128 + tid];
            g_aug[col * 128 + tid] = t;
        }
        __syncthreads();
        if (tid == 0) s_pv = g_aug[col * 128 + col];
        __syncthreads();
        if (tid < 128) g_aug[col * 128 + tid] /= s_pv;
        __syncthreads();
        if (tid < 64) s_f[tid] = (tid == col) ? 0.0 : g_aug[tid * 128 + col];
        __syncthreads();
        for (int idx = tid; idx < 64 * 128; idx += 256) {
            int r = idx >> 7, c = idx & 127;
            g_aug[idx] -= s_f[r] * g_aug[col * 128 + c];
        }
        __syncthreads();
    }
    for (int idx = tid; idx < 4096; idx += 256)
        g_Finv[idx] = (float)g_aug[(idx >> 6) * 128 + 64 + (idx & 63)];
    // tail fold: Wf = proj_w^T @ obj_emb @ m_eff @ out_w^T
    if (tid == 0) {
        float m = functor_w[0];
        for (int i = 1; i < 64; i++) m = fmaxf(m, functor_w[i]);
        float s = 0.f;
        for (int i = 0; i < 64; i++) { float e = expf(functor_w[i] - m); s_fw[i] = e; s += e; }
        for (int i = 0; i < 64; i++) s_fw[i] /= s;
    }
    __syncthreads();
    for (int idx = tid; idx < 4096; idx += 256) {  // m_eff
        float s = 0.f;
        for (int m = 0; m < 64; m++) s += s_fw[m] * morphisms[m * 4096 + idx];
        s_a[idx] = s;
    }
    __syncthreads();
    for (int idx = tid; idx < 4096; idx += 256) {  // A2 = obj_emb @ m_eff
        int k = idx >> 6, j = idx & 63;
        float s = 0.f;
        for (int i = 0; i < 64; i++) s += obj_emb[k * 64 + i] * s_a[i * 64 + j];
        s_b[idx] = s;
    }
    __syncthreads();
    for (int idx = tid; idx < 4096; idx += 256) {  // A3 = A2 @ out_w^T
        int k = idx >> 6, o = idx & 63;
        float s = 0.f;
        for (int j = 0; j < 64; j++) s += s_b[k * 64 + j] * out_w[o * 64 + j];
        s_a[idx] = s;
    }
    __syncthreads();
    for (int idx = tid; idx < 4096; idx += 256) {  // Wf = proj_w^T @ A3
        int t = idx >> 6, o = idx & 63;
        float s = 0.f;
        for (int k = 0; k < 64; k++) s += proj_w[k * 64 + t] * s_a[k * 64 + o];
        g_Wf[idx] = s;
    }
    if (tid < 64) {
        float s = out_b[tid];
        for (int k = 0; k < 64; k++) s += proj_b[k] * s_a[k * 64 + tid];
        g_bf[tid] = s;
    }
}

// ============ K0b: Dsym[p][o] = sum_k (C[i,j,k]+C[j,i,k]) * Wf[k][o] ============
__global__ void k0b(const float* __restrict__ conn) {
    __shared__ float Wsh[4096];
    int tid = threadIdx.x;
    for (int idx = tid; idx < 4096; idx += 256) Wsh[idx] = g_Wf[idx];
    __syncthreads();
    int idx = blockIdx.x * 256 + tid;
    int p = idx >> 6, o = idx & 63;
    int i = g_pi[p], j = g_pj[p];
    const float* c1 = conn + (i * 64 + j) * 64;
    const float* c2 = conn + (j * 64 + i) * 64;
    float s = 0.f;
    if (i == j) { for (int k = 0; k < 64; k++) s += c1[k] * Wsh[k * 64 + o]; }
    else { for (int k = 0; k < 64; k++) s += (c1[k] + c2[k]) * Wsh[k * 64 + o]; }
    g_Dsym[idx] = s;
}

// ============ K0c: KT[jd][o] = tk[o][jd] ============
__global__ void k0c(const float* __restrict__ tk) {
    int idx = blockIdx.x * 256 + threadIdx.x;
    int jd = idx >> 6, o = idx & 63;
    g_KT[jd * 64 + o] = tk[o * 768 + jd];
}

// ============ K_main: fully fused per-tile chain ============
// dyn smem: xm_sh[64*256] (64KB) + buf[6144] (24KB) = 88KB -> 2 CTAs/SM
#define STAGE(src, n4)                                                     \
    do {                                                                   \
        __syncthreads();                                                   \
        for (int _i = tid; _i < (n4); _i += 256)                           \
            ((float4*)buf)[_i] = ((const float4*)(src))[_i];               \
        __syncthreads();                                                   \
    } while (0)

__global__ void __launch_bounds__(256, 2) k_main(
    const float* __restrict__ pers, const float* __restrict__ qb,
    const float* __restrict__ kb, const float* __restrict__ vb,
    const float* __restrict__ ob, const float* __restrict__ ub,
    const float* __restrict__ sb, float* __restrict__ out) {
    extern __shared__ float sm[];
    float* xm_sh = sm;            // [64][256]
    float* buf = sm + 16384;      // 6144 floats
    __shared__ float ssm[512];    // biases + cos + bf
    int tid = threadIdx.x, b0 = blockIdx.x * 256;
    int b = b0 + tid;
    if (tid < 64) {
        ssm[tid] = qb[tid];        ssm[64 + tid] = kb[tid];
        ssm[128 + tid] = vb[tid];  ssm[192 + tid] = ob[tid];
        ssm[256 + tid] = ub[tid];  ssm[320 + tid] = sb[tid];
        ssm[384 + tid] = g_cosd[tid]; ssm[448 + tid] = g_bf[tid];
    }

    u64 acc[32];
    // ---- Stage 0: topo (streamed KT chunks of 32 j = 96 rows) ----
#pragma unroll
    for (int q = 0; q < 32; q++) acc[q] = 0ull;
    for (int c = 0; c < 8; c++) {
        STAGE(g_KT + c * 6144, 1536);
#pragma unroll 2
        for (int jj = 0; jj < 32; jj++) {
            int j = c * 32 + jj;
            size_t base = ((size_t)j * Bn + b) * 6;
            float2 a0 = __ldcs((const float2*)(pers + base));
            float2 a1 = __ldcs((const float2*)(pers + base + 2));
            float2 a2 = __ldcs((const float2*)(pers + base + 4));
            float sd[3] = {a0.x + a0.y, a1.x + a1.y, a2.x + a2.y};
#pragma unroll
            for (int d = 0; d < 3; d++) {
                u64 sv = pk2(sd[d], sd[d]);
                const ulonglong2* row = (const ulonglong2*)(buf + (jj * 3 + d) * 64);
#pragma unroll
                for (int q = 0; q < 16; q++) {
                    ulonglong2 w = row[q];
                    acc[2 * q] = ffma2(sv, w.x, acc[2 * q]);
                    acc[2 * q + 1] = ffma2(sv, w.y, acc[2 * q + 1]);
                }
            }
        }
    }
#pragma unroll
    for (int q = 0; q < 32; q++) {
        float lo, hi; upk2(acc[q], lo, hi);
        xm_sh[(2 * q) * 256 + tid] = lo;
        xm_sh[(2 * q + 1) * 256 + tid] = hi;
    }

    // ---- q = topo @ WqT + qb (registers) ----
    STAGE(g_WqT, 1024);
#pragma unroll
    for (int q = 0; q < 32; q++) acc[q] = 0ull;
    gemv64(xm_sh, buf, tid, acc);
    float qr[64];
#pragma unroll
    for (int q = 0; q < 32; q++) {
        float lo, hi; upk2(acc[q], lo, hi);
        qr[2 * q] = lo + ssm[2 * q];
        qr[2 * q + 1] = hi + ssm[2 * q + 1];
    }

    // ---- scores: k computed per 8-col chunk ----
    STAGE(g_WkT, 1024);
    float sc[64];
#pragma unroll
    for (int g = 0; g < 8; g++) {
        u64 ka[4] = {0, 0, 0, 0};
        gemv8(xm_sh, buf, g * 8, tid, ka);
        float k8[8];
#pragma unroll
        for (int q = 0; q < 4; q++) {
            float lo, hi; upk2(ka[q], lo, hi);
            k8[2 * q] = lo + ssm[64 + g * 8 + 2 * q];
            k8[2 * q + 1] = hi + ssm[64 + g * 8 + 2 * q + 1];
        }
#pragma unroll
        for (int h = 0; h < 8; h++) {
            float dot = 0.f;
#pragma unroll
            for (int d = 0; d < 8; d++) dot += qr[h * 8 + d] * k8[d];
            sc[h * 8 + g] = dot * ssm[384 + h * 8 + g] * 0.35355339059327373f;
        }
    }
    // softmax per head -> attW (reuse sc)
#pragma unroll
    for (int h = 0; h < 8; h++) {
        float m = sc[h * 8];
#pragma unroll
        for (int g = 1; g < 8; g++) m = fmaxf(m, sc[h * 8 + g]);
        float sum = 0.f;
#pragma unroll
        for (int g = 0; g < 8; g++) { float e = __expf(sc[h * 8 + g] - m); sc[h * 8 + g] = e; sum += e; }
        float inv = 1.0f / sum;
#pragma unroll
        for (int g = 0; g < 8; g++) sc[h * 8 + g] *= inv;
    }

    // ---- av = attW @ v, v per 8-col chunk ----
    STAGE(g_WvT, 1024);
    float av[64];
#pragma unroll
    for (int d = 0; d < 64; d++) av[d] = 0.f;
#pragma unroll
    for (int g = 0; g < 8; g++) {
        u64 va[4] = {0, 0, 0, 0};
        gemv8(xm_sh, buf, g * 8, tid, va);
        float v8[8];
#pragma unroll
        for (int q = 0; q < 4; q++) {
            float lo, hi; upk2(va[q], lo, hi);
            v8[2 * q] = lo + ssm[128 + g * 8 + 2 * q];
            v8[2 * q + 1] = hi + ssm[128 + g * 8 + 2 * q + 1];
        }
#pragma unroll
        for (int h = 0; h < 8; h++) {
            float w = sc[h * 8 + g];
#pragma unroll
            for (int d = 0; d < 8; d++) av[h * 8 + d] += w * v8[d];
        }
    }
#pragma unroll
    for (int i = 0; i < 64; i++) xm_sh[i * 256 + tid] = av[i];

    // ---- quantum = av @ WoT + ob -> xm_sh ----
    STAGE(g_WoT, 1024);
#pragma unroll
    for (int q = 0; q < 32; q++) acc[q] = 0ull;
    gemv64(xm_sh, buf, tid, acc);
#pragma unroll
    for (int q = 0; q < 32; q++) {
        float lo, hi; upk2(acc[q], lo, hi);
        xm_sh[(2 * q) * 256 + tid] = lo + ssm[192 + 2 * q];
        xm_sh[(2 * q + 1) * 256 + tid] = hi + ssm[192 + 2 * q + 1];
    }

    // ---- update gate (registers) ----
    STAGE(g_WuT, 1024);
#pragma unroll
    for (int q = 0; q < 32; q++) acc[q] = 0ull;
    gemv64(xm_sh, buf, tid, acc);
    float ur[64];
#pragma unroll
    for (int q = 0; q < 32; q++) {
        float lo, hi; upk2(acc[q], lo, hi);
        ur[2 * q] = fast_sigmoid(lo + ssm[256 + 2 * q]);
        ur[2 * q + 1] = fast_sigmoid(hi + ssm[256 + 2 * q + 1]);
    }

    // ---- cand = tanh(...) -> xm_sh ----
    STAGE(g_WsT, 1024);
#pragma unroll
    for (int q = 0; q < 32; q++) acc[q] = 0ull;
    gemv64(xm_sh, buf, tid, acc);
#pragma unroll
    for (int q = 0; q < 32; q++) {
        float lo, hi; upk2(acc[q], lo, hi);
        xm_sh[(2 * q) * 256 + tid] = fast_tanh(lo + ssm[320 + 2 * q]);
        xm_sh[(2 * q + 1) * 256 + tid] = fast_tanh(hi + ssm[320 + 2 * q + 1]);
    }

    // ---- h = u * (Finv @ cand) -> xm_sh ----
    STAGE(g_Finv, 1024);
#pragma unroll
    for (int q = 0; q < 32; q++) acc[q] = 0ull;
    gemv64(xm_sh, buf, tid, acc);
#pragma unroll
    for (int q = 0; q < 32; q++) {
        float lo, hi; upk2(acc[q], lo, hi);
        xm_sh[(2 * q) * 256 + tid] = lo * ur[2 * q];
        xm_sh[(2 * q + 1) * 256 + tid] = hi * ur[2 * q + 1];
    }

    // ---- xm = h @ metric -> xm_sh ----
    STAGE(g_metric, 1024);
#pragma unroll
    for (int q = 0; q < 32; q++) acc[q] = 0ull;
    gemv64(xm_sh, buf, tid, acc);
#pragma unroll
    for (int q = 0; q < 32; q++) {
        float lo, hi; upk2(acc[q], lo, hi);
        xm_sh[(2 * q) * 256 + tid] = lo;
        xm_sh[(2 * q + 1) * 256 + tid] = hi;
    }

    // ---- out = bf + xm@Wf + sum_p (xm_i*xm_j)*Dsym[p,:] ----
    STAGE(g_Wf, 1024);
#pragma unroll
    for (int q = 0; q < 32; q++) acc[q] = 0ull;
    gemv64(xm_sh, buf, tid, acc);
    int pi = 0, pj = 0;
    for (int c0 = 0; c0 < NP; c0 += 96) {
        int nch = min(96, NP - c0);
        STAGE(g_Dsym + c0 * 64, nch * 16);
        for (int p = 0; p < nch; p++) {
            float prod = xm_sh[pi * 256 + tid] * xm_sh[pj * 256 + tid];
            u64 pv = pk2(prod, prod);
            const ulonglong2* row = (const ulonglong2*)(buf + p * 64);
#pragma unroll
            for (int q = 0; q < 16; q++) {
                ulonglong2 w = row[q];
                acc[2 * q] = ffma2(pv, w.x, acc[2 * q]);
                acc[2 * q + 1] = ffma2(pv, w.y, acc[2 * q + 1]);
            }
            pj++;
            if (pj == 64) { pi++; pj = pi; }
        }
    }
    float4* orow = (float4*)(out + (size_t)b * 64);
#pragma unroll
    for (int q = 0; q < 16; q++) {
        float a0, a1, a2, a3;
        upk2(acc[2 * q], a0, a1);
        upk2(acc[2 * q + 1], a2, a3);
        orow[q] = make_float4(a0 + ssm[448 + 4 * q], a1 + ssm[448 + 4 * q + 1],
                              a2 + ssm[448 + 4 * q + 2], a3 + ssm[448 + 4 * q + 3]);
    }
}

extern "C" void kernel_launch(void* const* d_in, const int* in_sizes, int n_in,
                              void* d_out, int out_size) {
    const float* pers     = (const float*)d_in[1];
    const float* tk       = (const float*)d_in[2];
    const float* q_w = (const float*)d_in[3],  *q_b = (const float*)d_in[4];
    const float* k_w = (const float*)d_in[5],  *k_b = (const float*)d_in[6];
    const float* v_w = (const float*)d_in[7],  *v_b = (const float*)d_in[8];
    const float* o_w = (const float*)d_in[9],  *o_b = (const float*)d_in[10];
    const float* phase = (const float*)d_in[11];
    const float* update_w = (const float*)d_in[12], *update_b = (const float*)d_in[13];
    const float* state_w  = (const float*)d_in[16], *state_b  = (const float*)d_in[17];
    const float* fisher_m = (const float*)d_in[18];
    const float* metric_m = (const float*)d_in[19];
    const float* connection = (const float*)d_in[20];
    const float* proj_w = (const float*)d_in[21], *proj_b = (const float*)d_in[22];
    const float* obj_emb = (const float*)d_in[23];
    const float* morphisms = (const float*)d_in[24];
    const float* functor_w = (const float*)d_in[25];
    const float* out_w = (const float*)d_in[26], *out_b = (const float*)d_in[27];
    float* out = (float*)d_out;

    static bool attr_set = false;
    if (!attr_set) {
        cudaFuncSetAttribute(k_main, cudaFuncAttributeMaxDynamicSharedMemorySize,
                             (16384 + 6144) * 4);
        attr_set = true;
    }
    k0a<<<1, 256>>>(phase, q_w, k_w, v_w, o_w, update_w, state_w, fisher_m, metric_m,
                    proj_w, proj_b, obj_emb, morphisms, functor_w, out_w, out_b);
    k0b<<<NP * 64 / 256, 256>>>(connection);
    k0c<<<768 * 64 / 256, 256>>>(tk);
    k_main<<<Bn / 256, 256, (16384 + 6144) * 4>>>(pers, q_b, k_b, v_b, o_b, update_b,
                                                  state_b, out);
}

// round 10
// speedup vs baseline: 1.6490x; 1.6490x over previous
#include <cuda_runtime.h>
#include <math.h>

#define Bn 65536
#define NP 2080  // 64*65/2 pairs i<=j

// ---------- device scratch ----------
__device__ float g_cosd[64], g_Finv[4096], g_metric[4096], g_Wf[4096], g_bf[64];
__device__ float g_Dsym[NP * 64];
__device__ float g_WqT[4096], g_WkT[4096], g_WvT[4096], g_WoT[4096], g_WuT[4096], g_WsT[4096];
__device__ float g_KT[768 * 64];
__device__ double g_aug[64 * 128];
__device__ float g_topo[64 * Bn], g_qv[64 * Bn], g_kv[64 * Bn], g_vv[64 * Bn];
__device__ float g_quant[64 * Bn], g_xm[64 * Bn];

// ---------- packed f32x2 ----------
typedef unsigned long long u64;
__device__ __forceinline__ u64 pk2(float lo, float hi) {
    u64 r; asm("mov.b64 %0, {%1, %2};" : "=l"(r) : "f"(lo), "f"(hi)); return r;
}
__device__ __forceinline__ void upk2(u64 v, float& lo, float& hi) {
    asm("mov.b64 {%0, %1}, %2;" : "=f"(lo), "=f"(hi) : "l"(v));
}
__device__ __forceinline__ u64 ffma2(u64 a, u64 b, u64 c) {
    u64 d; asm("fma.rn.f32x2 %0, %1, %2, %3;" : "=l"(d) : "l"(a), "l"(b), "l"(c)); return d;
}
// acc[0..15] (32 outputs ob..ob+31) += xsh[i*128+lt] * W[i*64+ob+o]
__device__ __forceinline__ void gemv32(const float* xsh, const float* W, int lt, int ob,
                                       u64 acc[16]) {
#pragma unroll 4
    for (int i = 0; i < 64; i++) {
        float x = xsh[i * 128 + lt];
        u64 xv = pk2(x, x);
        const ulonglong2* row = (const ulonglong2*)(W + i * 64 + ob);
#pragma unroll
        for (int q = 0; q < 8; q++) {
            ulonglong2 w = row[q];
            acc[2 * q] = ffma2(xv, w.x, acc[2 * q]);
            acc[2 * q + 1] = ffma2(xv, w.y, acc[2 * q + 1]);
        }
    }
}

#define STAGE(dst, src, n4)                                    \
    do {                                                       \
        __syncthreads();                                       \
        for (int _i = tid; _i < (n4); _i += 256)               \
            ((float4*)(dst))[_i] = ((const float4*)(src))[_i]; \
        __syncthreads();                                       \
    } while (0)

// ============ K0a: single-CTA precompute ============
__global__ void k0a(const float* __restrict__ phase, const float* __restrict__ q_w,
                    const float* __restrict__ k_w, const float* __restrict__ v_w,
                    const float* __restrict__ o_w, const float* __restrict__ update_w,
                    const float* __restrict__ state_w, const float* __restrict__ fisher_m,
                    const float* __restrict__ metric_m, const float* __restrict__ proj_w,
                    const float* __restrict__ proj_b, const float* __restrict__ obj_emb,
                    const float* __restrict__ morphisms, const float* __restrict__ functor_w,
                    const float* __restrict__ out_w, const float* __restrict__ out_b) {
    __shared__ float s_a[4096], s_b[4096], s_fw[64];
    __shared__ double s_f[64], s_bv[2], s_pv;
    __shared__ int s_br[2], s_piv;
    int tid = threadIdx.x;
    if (tid < 64) g_cosd[tid] = cosf(phase[tid >> 3] - phase[tid & 7]);
    for (int idx = tid; idx < 4096; idx += 256) {
        int o = idx >> 6, i = idx & 63;
        g_WqT[i * 64 + o] = q_w[idx];  g_WkT[i * 64 + o] = k_w[idx];
        g_WvT[i * 64 + o] = v_w[idx];  g_WoT[i * 64 + o] = o_w[idx];
        g_WuT[i * 64 + o] = update_w[o * 128 + i];  // h0=0: only first half
        g_WsT[i * 64 + o] = state_w[o * 128 + i];
    }
    for (int idx = tid; idx < 4096; idx += 256) {
        int i = idx >> 6, j = idx & 63;
        float sf = 0.f, sm = 0.f;
        for (int k = 0; k < 64; k++) {
            sf += fisher_m[i * 64 + k] * fisher_m[j * 64 + k];
            sm += metric_m[i * 64 + k] * metric_m[j * 64 + k];
        }
        g_metric[idx] = sm;
        g_aug[i * 128 + j] = (double)sf;
        g_aug[i * 128 + 64 + j] = (j == i) ? 1.0 : 0.0;
    }
    __syncthreads();
    // Gauss-Jordan (fp64, partial pivot); columns < col are already e-vectors
    for (int col = 0; col < 64; col++) {
        if (tid < 64) {
            double v = (tid >= col) ? fabs(g_aug[tid * 128 + col]) : -1.0;
            int r = tid;
            for (int off = 16; off; off >>= 1) {
                double ov = __shfl_down_sync(0xffffffffu, v, off);
                int orr = __shfl_down_sync(0xffffffffu, r, off);
                if (ov > v) { v = ov; r = orr; }
            }
            if ((tid & 31) == 0) { s_bv[tid >> 5] = v; s_br[tid >> 5] = r; }
        }
        __syncthreads();
        if (tid == 0) s_piv = (s_bv[1] > s_bv[0]) ? s_br[1] : s_br[0];
        __syncthreads();
        int piv = s_piv;
        int ncol = 128 - col;
        if (piv != col && tid < ncol) {
            int c = col + tid;
            double t = g_aug[piv * 128 + c];
            g_aug[piv * 128 + c] = g_aug[col * 128 + c];
            g_aug[col * 128 + c] = t;
        }
        __syncthreads();
        if (tid == 0) s_pv = g_aug[col * 128 + col];
        __syncthreads();
        if (tid < ncol) g_aug[col * 128 + col + tid] /= s_pv;
        __syncthreads();
        if (tid < 64) s_f[tid] = (tid == col) ? 0.0 : g_aug[tid * 128 + col];
        __syncthreads();
        int total = 64 * ncol;
        for (int t = tid; t < total; t += 256) {
            int r = t / ncol, c = col + (t - r * ncol);
            g_aug[r * 128 + c] -= s_f[r] * g_aug[col * 128 + c];
        }
        __syncthreads();
    }
    for (int idx = tid; idx < 4096; idx += 256)
        g_Finv[idx] = (float)g_aug[(idx >> 6) * 128 + 64 + (idx & 63)];
    // tail fold: Wf = proj_w^T @ obj_emb @ m_eff @ out_w^T
    if (tid == 0) {
        float m = functor_w[0];
        for (int i = 1; i < 64; i++) m = fmaxf(m, functor_w[i]);
        float s = 0.f;
        for (int i = 0; i < 64; i++) { float e = expf(functor_w[i] - m); s_fw[i] = e; s += e; }
        for (int i = 0; i < 64; i++) s_fw[i] /= s;
    }
    __syncthreads();
    for (int idx = tid; idx < 4096; idx += 256) {  // m_eff
        float s = 0.f;
        for (int m = 0; m < 64; m++) s += s_fw[m] * morphisms[m * 4096 + idx];
        s_a[idx] = s;
    }
    __syncthreads();
    for (int idx = tid; idx < 4096; idx += 256) {  // A2 = obj_emb @ m_eff
        int k = idx >> 6, j = idx & 63;
        float s = 0.f;
        for (int i = 0; i < 64; i++) s += obj_emb[k * 64 + i] * s_a[i * 64 + j];
        s_b[idx] = s;
    }
    __syncthreads();
    for (int idx = tid; idx < 4096; idx += 256) {  // A3 = A2 @ out_w^T
        int k = idx >> 6, o = idx & 63;
        float s = 0.f;
        for (int j = 0; j < 64; j++) s += s_b[k * 64 + j] * out_w[o * 64 + j];
        s_a[idx] = s;
    }
    __syncthreads();
    for (int idx = tid; idx < 4096; idx += 256) {  // Wf = proj_w^T @ A3
        int t = idx >> 6, o = idx & 63;
        float s = 0.f;
        for (int k = 0; k < 64; k++) s += proj_w[k * 64 + t] * s_a[k * 64 + o];
        g_Wf[idx] = s;
    }
    if (tid < 64) {
        float s = out_b[tid];
        for (int k = 0; k < 64; k++) s += proj_b[k] * s_a[k * 64 + tid];
        g_bf[tid] = s;
    }
}

// ============ K0b: Dsym[p][o] = sum_k (C[i,j,k]+C[j,i,k]) * Wf[k][o] ============
__global__ void k0b(const float* __restrict__ conn) {
    __shared__ float Wsh[4096];
    int tid = threadIdx.x;
    for (int idx = tid; idx < 4096; idx += 256) Wsh[idx] = g_Wf[idx];
    __syncthreads();
    int idx = blockIdx.x * 256 + tid;
    int p = idx >> 6, o = idx & 63;
    // decode pair p -> (i,j), i<=j
    int i = 0, rem = p;
    while (rem >= 64 - i) { rem -= 64 - i; i++; }
    int j = i + rem;
    const float* c1 = conn + (i * 64 + j) * 64;
    const float* c2 = conn + (j * 64 + i) * 64;
    float s = 0.f;
    if (i == j) { for (int k = 0; k < 64; k++) s += c1[k] * Wsh[k * 64 + o]; }
    else { for (int k = 0; k < 64; k++) s += (c1[k] + c2[k]) * Wsh[k * 64 + o]; }
    g_Dsym[idx] = s;
}

// ============ K0c: KT[jd][o] = tk[o][jd] ============
__global__ void k0c(const float* __restrict__ tk) {
    int idx = blockIdx.x * 256 + threadIdx.x;
    int jd = idx >> 6, o = idx & 63;
    g_KT[jd * 64 + o] = tk[o * 768 + jd];
}

// ============ K1: topo ============
__global__ void __launch_bounds__(256, 3) k_topo(const float* __restrict__ pers) {
    extern __shared__ float buf[];  // 6144 floats (32 jd = 96 rows)
    int tid = threadIdx.x, lt = tid & 127, ob = (tid >> 7) * 32;
    int b = blockIdx.x * 128 + lt;
    u64 acc[16];
#pragma unroll
    for (int q = 0; q < 16; q++) acc[q] = 0ull;
    for (int c = 0; c < 8; c++) {
        STAGE(buf, g_KT + c * 6144, 1536);
#pragma unroll 2
        for (int jj = 0; jj < 32; jj++) {
            int j = c * 32 + jj;
            size_t base = ((size_t)j * Bn + b) * 6;
            float2 a0 = __ldcs((const float2*)(pers + base));
            float2 a1 = __ldcs((const float2*)(pers + base + 2));
            float2 a2 = __ldcs((const float2*)(pers + base + 4));
            float sd[3] = {a0.x + a0.y, a1.x + a1.y, a2.x + a2.y};
#pragma unroll
            for (int d = 0; d < 3; d++) {
                u64 sv = pk2(sd[d], sd[d]);
                const ulonglong2* row = (const ulonglong2*)(buf + (jj * 3 + d) * 64 + ob);
#pragma unroll
                for (int q = 0; q < 8; q++) {
                    ulonglong2 w = row[q];
                    acc[2 * q] = ffma2(sv, w.x, acc[2 * q]);
                    acc[2 * q + 1] = ffma2(sv, w.y, acc[2 * q + 1]);
                }
            }
        }
    }
#pragma unroll
    for (int q = 0; q < 16; q++) {
        float lo, hi; upk2(acc[q], lo, hi);
        g_topo[(ob + 2 * q) * Bn + b] = lo;
        g_topo[(ob + 2 * q + 1) * Bn + b] = hi;
    }
}

// ============ K2: q/k/v ============
__global__ void __launch_bounds__(256, 3) k_qkv(const float* __restrict__ qb,
                                                const float* __restrict__ kb,
                                                const float* __restrict__ vb) {
    extern __shared__ float sm[];
    float* in_sh = sm;          // 8192
    float* buf = sm + 8192;     // 4096
    __shared__ float bsh[192];
    int tid = threadIdx.x, lt = tid & 127, ob = (tid >> 7) * 32;
    int b0 = blockIdx.x * 128, b = b0 + lt;
    if (tid < 64) { bsh[tid] = qb[tid]; bsh[64 + tid] = kb[tid]; bsh[128 + tid] = vb[tid]; }
    for (int idx = tid; idx < 8192; idx += 256)
        in_sh[idx] = g_topo[(idx >> 7) * Bn + b0 + (idx & 127)];
    const float* Wg[3] = {g_WqT, g_WkT, g_WvT};
    float* outg[3] = {g_qv, g_kv, g_vv};
    for (int s = 0; s < 3; s++) {
        STAGE(buf, Wg[s], 1024);
        u64 acc[16];
#pragma unroll
        for (int q = 0; q < 16; q++) acc[q] = 0ull;
        gemv32(in_sh, buf, lt, ob, acc);
#pragma unroll
        for (int q = 0; q < 16; q++) {
            float lo, hi; upk2(acc[q], lo, hi);
            outg[s][(ob + 2 * q) * Bn + b] = lo + bsh[s * 64 + ob + 2 * q];
            outg[s][(ob + 2 * q + 1) * Bn + b] = hi + bsh[s * 64 + ob + 2 * q + 1];
        }
    }
}

// ============ K3: attention + o-proj ============
__global__ void __launch_bounds__(256, 2) k_att(const float* __restrict__ ob_bias) {
    extern __shared__ float sm[];
    float* k_sh = sm;            // 8192
    float* v_sh = sm + 8192;     // 8192
    float* buf = sm + 16384;     // 4096 (WoT)
    __shared__ float cos_sh[64], obb[64];
    int tid = threadIdx.x, lt = tid & 127, ob = (tid >> 7) * 32;
    int b0 = blockIdx.x * 128, b = b0 + lt;
    if (tid < 64) { cos_sh[tid] = g_cosd[tid]; obb[tid] = ob_bias[tid]; }
    for (int idx = tid; idx < 8192; idx += 256) {
        int i = idx >> 7, c = idx & 127;
        k_sh[idx] = g_kv[i * Bn + b0 + c];
        v_sh[idx] = g_vv[i * Bn + b0 + c];
    }
    STAGE(buf, g_WoT, 1024);
    u64 acc[16];
#pragma unroll
    for (int q = 0; q < 16; q++) acc[q] = 0ull;
    for (int h = 0; h < 8; h++) {
        float qh[8];
#pragma unroll
        for (int d = 0; d < 8; d++) qh[d] = g_qv[(h * 8 + d) * Bn + b];
        float s[8];
#pragma unroll
        for (int g = 0; g < 8; g++) {
            float dot = 0.f;
#pragma unroll
            for (int d = 0; d < 8; d++) dot += qh[d] * k_sh[(g * 8 + d) * 128 + lt];
            s[g] = dot * cos_sh[h * 8 + g] * 0.35355339059327373f;
        }
        float m = s[0];
#pragma unroll
        for (int g = 1; g < 8; g++) m = fmaxf(m, s[g]);
        float sum = 0.f;
#pragma unroll
        for (int g = 0; g < 8; g++) { s[g] = expf(s[g] - m); sum += s[g]; }
        float inv = 1.0f / sum;
        float av8[8] = {0, 0, 0, 0, 0, 0, 0, 0};
#pragma unroll
        for (int g = 0; g < 8; g++) {
            float w = s[g] * inv;
#pragma unroll
            for (int d = 0; d < 8; d++) av8[d] += w * v_sh[(g * 8 + d) * 128 + lt];
        }
#pragma unroll
        for (int d = 0; d < 8; d++) {
            u64 xv = pk2(av8[d], av8[d]);
            const ulonglong2* row = (const ulonglong2*)(buf + (h * 8 + d) * 64 + ob);
#pragma unroll
            for (int q = 0; q < 8; q++) {
                ulonglong2 w = row[q];
                acc[2 * q] = ffma2(xv, w.x, acc[2 * q]);
                acc[2 * q + 1] = ffma2(xv, w.y, acc[2 * q + 1]);
            }
        }
    }
#pragma unroll
    for (int q = 0; q < 16; q++) {
        float lo, hi; upk2(acc[q], lo, hi);
        g_quant[(ob + 2 * q) * Bn + b] = lo + obb[ob + 2 * q];
        g_quant[(ob + 2 * q + 1) * Bn + b] = hi + obb[ob + 2 * q + 1];
    }
}

// ============ K4: update+cand+Finv+metric fused ============
__global__ void __launch_bounds__(256, 2) k_ucx(const float* __restrict__ ub,
                                                const float* __restrict__ sb) {
    extern __shared__ float sm[];
    float* in_sh = sm;          // 8192
    float* c_sh = sm + 8192;    // 8192
    float* buf = sm + 16384;    // 4096
    __shared__ float bsh[128];
    int tid = threadIdx.x, lt = tid & 127, ob = (tid >> 7) * 32;
    int b0 = blockIdx.x * 128, b = b0 + lt;
    if (tid < 64) { bsh[tid] = ub[tid]; bsh[64 + tid] = sb[tid]; }
    for (int idx = tid; idx < 8192; idx += 256)
        in_sh[idx] = g_quant[(idx >> 7) * Bn + b0 + (idx & 127)];
    // update gate
    STAGE(buf, g_WuT, 1024);
    u64 acc[16];
#pragma unroll
    for (int q = 0; q < 16; q++) acc[q] = 0ull;
    gemv32(in_sh, buf, lt, ob, acc);
    float ur[32];
#pragma unroll
    for (int q = 0; q < 16; q++) {
        float lo, hi; upk2(acc[q], lo, hi);
        ur[2 * q] = 1.0f / (1.0f + expf(-(lo + bsh[ob + 2 * q])));
        ur[2 * q + 1] = 1.0f / (1.0f + expf(-(hi + bsh[ob + 2 * q + 1])));
    }
    // candidate
    STAGE(buf, g_WsT, 1024);
#pragma unroll
    for (int q = 0; q < 16; q++) acc[q] = 0ull;
    gemv32(in_sh, buf, lt, ob, acc);
#pragma unroll
    for (int q = 0; q < 16; q++) {
        float lo, hi; upk2(acc[q], lo, hi);
        c_sh[(ob + 2 * q) * 128 + lt] = tanhf(lo + bsh[64 + ob + 2 * q]);
        c_sh[(ob + 2 * q + 1) * 128 + lt] = tanhf(hi + bsh[64 + ob + 2 * q + 1]);
    }
    // h = u * (Finv @ cand)
    STAGE(buf, g_Finv, 1024);
#pragma unroll
    for (int q = 0; q < 16; q++) acc[q] = 0ull;
    gemv32(c_sh, buf, lt, ob, acc);
#pragma unroll
    for (int q = 0; q < 16; q++) {
        float lo, hi; upk2(acc[q], lo, hi);
        in_sh[(ob + 2 * q) * 128 + lt] = lo * ur[2 * q];
        in_sh[(ob + 2 * q + 1) * 128 + lt] = hi * ur[2 * q + 1];
    }
    // xm = h @ metric
    STAGE(buf, g_metric, 1024);
#pragma unroll
    for (int q = 0; q < 16; q++) acc[q] = 0ull;
    gemv32(in_sh, buf, lt, ob, acc);
#pragma unroll
    for (int q = 0; q < 16; q++) {
        float lo, hi; upk2(acc[q], lo, hi);
        g_xm[(ob + 2 * q) * Bn + b] = lo;
        g_xm[(ob + 2 * q + 1) * Bn + b] = hi;
    }
}

// ============ K5: out = bf + xm@Wf + sum_p (xm_i*xm_j)*Dsym[p,:] ============
__global__ void __launch_bounds__(256, 3) k_bil(float* __restrict__ out) {
    extern __shared__ float sm[];
    float* in_sh = sm;          // 8192
    float* buf = sm + 8192;     // 4096
    __shared__ float bf_sh[64];
    int tid = threadIdx.x, lt = tid & 127, ob = (tid >> 7) * 32;
    int b0 = blockIdx.x * 128, b = b0 + lt;
    if (tid < 64) bf_sh[tid] = g_bf[tid];
    for (int idx = tid; idx < 8192; idx += 256)
        in_sh[idx] = g_xm[(idx >> 7) * Bn + b0 + (idx & 127)];
    STAGE(buf, g_Wf, 1024);
    u64 acc[16];
#pragma unroll
    for (int q = 0; q < 16; q++) acc[q] = 0ull;
    gemv32(in_sh, buf, lt, ob, acc);
    int pi = 0, pj = 0;
    float xi = in_sh[lt];  // x[0]
    for (int c0 = 0; c0 < NP; c0 += 64) {
        int nch = min(64, NP - c0);
        STAGE(buf, g_Dsym + c0 * 64, nch * 16);
        for (int p = 0; p < nch; p++) {
            float prod = xi * in_sh[pj * 128 + lt];
            u64 pv = pk2(prod, prod);
            const ulonglong2* row = (const ulonglong2*)(buf + p * 64 + ob);
#pragma unroll
            for (int q = 0; q < 8; q++) {
                ulonglong2 w = row[q];
                acc[2 * q] = ffma2(pv, w.x, acc[2 * q]);
                acc[2 * q + 1] = ffma2(pv, w.y, acc[2 * q + 1]);
            }
            pj++;
            if (pj == 64) { pi++; pj = pi; xi = in_sh[pi * 128 + lt]; }
        }
    }
    float4* orow = (float4*)(out + (size_t)b * 64 + ob);
#pragma unroll
    for (int q = 0; q < 8; q++) {
        float a0, a1, a2, a3;
        upk2(acc[2 * q], a0, a1);
        upk2(acc[2 * q + 1], a2, a3);
        orow[q] = make_float4(a0 + bf_sh[ob + 4 * q], a1 + bf_sh[ob + 4 * q + 1],
                              a2 + bf_sh[ob + 4 * q + 2], a3 + bf_sh[ob + 4 * q + 3]);
    }
}

extern "C" void kernel_launch(void* const* d_in, const int* in_sizes, int n_in,
                              void* d_out, int out_size) {
    const float* pers     = (const float*)d_in[1];
    const float* tk       = (const float*)d_in[2];
    const float* q_w = (const float*)d_in[3],  *q_b = (const float*)d_in[4];
    const float* k_w = (const float*)d_in[5],  *k_b = (const float*)d_in[6];
    const float* v_w = (const float*)d_in[7],  *v_b = (const float*)d_in[8];
    const float* o_w = (const float*)d_in[9],  *o_b = (const float*)d_in[10];
    const float* phase = (const float*)d_in[11];
    const float* update_w = (const float*)d_in[12], *update_b = (const float*)d_in[13];
    const float* state_w  = (const float*)d_in[16], *state_b  = (const float*)d_in[17];
    const float* fisher_m = (const float*)d_in[18];
    const float* metric_m = (const float*)d_in[19];
    const float* connection = (const float*)d_in[20];
    const float* proj_w = (const float*)d_in[21], *proj_b = (const float*)d_in[22];
    const float* obj_emb = (const float*)d_in[23];
    const float* morphisms = (const float*)d_in[24];
    const float* functor_w = (const float*)d_in[25];
    const float* out_w = (const float*)d_in[26], *out_b = (const float*)d_in[27];
    float* out = (float*)d_out;

    static bool inited = false;
    static cudaStream_t s2;
    static cudaEvent_t ev1, ev2;
    if (!inited) {
        cudaFuncSetAttribute(k_topo, cudaFuncAttributeMaxDynamicSharedMemorySize, 6144 * 4);
        cudaFuncSetAttribute(k_qkv, cudaFuncAttributeMaxDynamicSharedMemorySize, 12288 * 4);
        cudaFuncSetAttribute(k_att, cudaFuncAttributeMaxDynamicSharedMemorySize, 20480 * 4);
        cudaFuncSetAttribute(k_ucx, cudaFuncAttributeMaxDynamicSharedMemorySize, 20480 * 4);
        cudaFuncSetAttribute(k_bil, cudaFuncAttributeMaxDynamicSharedMemorySize, 12288 * 4);
        cudaStreamCreateWithFlags(&s2, cudaStreamNonBlocking);
        cudaEventCreateWithFlags(&ev1, cudaEventDisableTiming);
        cudaEventCreateWithFlags(&ev2, cudaEventDisableTiming);
        inited = true;
    }
    const int grid = Bn / 128;  // 512
    // fork: precompute (k0a,k0b) runs under k_topo
    cudaEventRecord(ev1, 0);
    cudaStreamWaitEvent(s2, ev1, 0);
    k0a<<<1, 256, 0, s2>>>(phase, q_w, k_w, v_w, o_w, update_w, state_w, fisher_m,
                           metric_m, proj_w, proj_b, obj_emb, morphisms, functor_w,
                           out_w, out_b);
    k0b<<<NP * 64 / 256, 256, 0, s2>>>(connection);
    cudaEventRecord(ev2, s2);
    k0c<<<768 * 64 / 256, 256>>>(tk);
    k_topo<<<grid, 256, 6144 * 4>>>(pers);
    cudaStreamWaitEvent(0, ev2, 0);  // join before weights are needed
    k_qkv<<<grid, 256, 12288 * 4>>>(q_b, k_b, v_b);
    k_att<<<grid, 256, 20480 * 4>>>(o_b);
    k_ucx<<<grid, 256, 20480 * 4>>>(update_b, state_b);
    k_bil<<<grid, 256, 12288 * 4>>>(out);
}

// round 12
// speedup vs baseline: 1.9625x; 1.1902x over previous
#include <cuda_runtime.h>
#include <math.h>

#define Bn 65536
#define NP 2080  // 64*65/2 pairs i<=j

// ---------- device scratch ----------
__device__ float g_cosd[64], g_Finv[4096], g_metric[4096], g_Wf[4096], g_bf[64];
__device__ float g_Dsym[NP * 64];
__device__ float g_WqT[4096], g_WkT[4096], g_WvT[4096], g_WoT[4096], g_WuT[4096], g_WsT[4096];
__device__ float g_KT[768 * 64];
__device__ double g_aug[64 * 128];
__device__ float g_topo[64 * Bn], g_qv[64 * Bn], g_kv[64 * Bn], g_vv[64 * Bn];
__device__ float g_quant[64 * Bn], g_xm[64 * Bn];

// ---------- packed f32x2 ----------
typedef unsigned long long u64;
__device__ __forceinline__ u64 pk2(float lo, float hi) {
    u64 r; asm("mov.b64 %0, {%1, %2};" : "=l"(r) : "f"(lo), "f"(hi)); return r;
}
__device__ __forceinline__ void upk2(u64 v, float& lo, float& hi) {
    asm("mov.b64 {%0, %1}, %2;" : "=f"(lo), "=f"(hi) : "l"(v));
}
__device__ __forceinline__ u64 ffma2(u64 a, u64 b, u64 c) {
    u64 d; asm("fma.rn.f32x2 %0, %1, %2, %3;" : "=l"(d) : "l"(a), "l"(b), "l"(c)); return d;
}
// 1-elem: acc[0..15] (32 outputs ob..) += xsh[i*128+lt] * W[i*64+ob+o]
__device__ __forceinline__ void gemv32(const float* xsh, const float* W, int lt, int ob,
                                       u64 acc[16]) {
#pragma unroll 4
    for (int i = 0; i < 64; i++) {
        float x = xsh[i * 128 + lt];
        u64 xv = pk2(x, x);
        const ulonglong2* row = (const ulonglong2*)(W + i * 64 + ob);
#pragma unroll
        for (int q = 0; q < 8; q++) {
            ulonglong2 w = row[q];
            acc[2 * q] = ffma2(xv, w.x, acc[2 * q]);
            acc[2 * q + 1] = ffma2(xv, w.y, acc[2 * q + 1]);
        }
    }
}
// 2-elem: xsh stride 256; elems lt and lt+128
__device__ __forceinline__ void gemv32x2(const float* xsh, const float* W, int lt, int ob,
                                         u64 a1[16], u64 a2[16]) {
#pragma unroll 2
    for (int i = 0; i < 64; i++) {
        float x1 = xsh[i * 256 + lt], x2 = xsh[i * 256 + 128 + lt];
        u64 v1 = pk2(x1, x1), v2 = pk2(x2, x2);
        const ulonglong2* row = (const ulonglong2*)(W + i * 64 + ob);
#pragma unroll
        for (int q = 0; q < 8; q++) {
            ulonglong2 w = row[q];
            a1[2 * q] = ffma2(v1, w.x, a1[2 * q]);
            a1[2 * q + 1] = ffma2(v1, w.y, a1[2 * q + 1]);
            a2[2 * q] = ffma2(v2, w.x, a2[2 * q]);
            a2[2 * q + 1] = ffma2(v2, w.y, a2[2 * q + 1]);
        }
    }
}

#define STAGE(dst, src, n4)                                    \
    do {                                                       \
        __syncthreads();                                       \
        for (int _i = tid; _i < (n4); _i += 256)               \
            ((float4*)(dst))[_i] = ((const float4*)(src))[_i]; \
        __syncthreads();                                       \
    } while (0)

// ============ K0a: single-CTA precompute ============
__global__ void k0a(const float* __restrict__ phase, const float* __restrict__ q_w,
                    const float* __restrict__ k_w, const float* __restrict__ v_w,
                    const float* __restrict__ o_w, const float* __restrict__ update_w,
                    const float* __restrict__ state_w, const float* __restrict__ fisher_m,
                    const float* __restrict__ metric_m, const float* __restrict__ proj_w,
                    const float* __restrict__ proj_b, const float* __restrict__ obj_emb,
                    const float* __restrict__ morphisms, const float* __restrict__ functor_w,
                    const float* __restrict__ out_w, const float* __restrict__ out_b) {
    __shared__ float s_a[4096], s_b[4096], s_fw[64];
    __shared__ double s_f[64], s_bv[2], s_pv;
    __shared__ int s_br[2], s_piv;
    int tid = threadIdx.x;
    if (tid < 64) g_cosd[tid] = cosf(phase[tid >> 3] - phase[tid & 7]);
    for (int idx = tid; idx < 4096; idx += 256) {
        int o = idx >> 6, i = idx & 63;
        g_WqT[i * 64 + o] = q_w[idx];  g_WkT[i * 64 + o] = k_w[idx];
        g_WvT[i * 64 + o] = v_w[idx];  g_WoT[i * 64 + o] = o_w[idx];
        g_WuT[i * 64 + o] = update_w[o * 128 + i];  // h0=0: only first half
        g_WsT[i * 64 + o] = state_w[o * 128 + i];
    }
    for (int idx = tid; idx < 4096; idx += 256) {
        int i = idx >> 6, j = idx & 63;
        float sf = 0.f, sm = 0.f;
        for (int k = 0; k < 64; k++) {
            sf += fisher_m[i * 64 + k] * fisher_m[j * 64 + k];
            sm += metric_m[i * 64 + k] * metric_m[j * 64 + k];
        }
        g_metric[idx] = sm;
        g_aug[i * 128 + j] = (double)sf;
        g_aug[i * 128 + 64 + j] = (j == i) ? 1.0 : 0.0;
    }
    __syncthreads();
    // Gauss-Jordan (fp64, partial pivot); columns < col already e-vectors
    for (int col = 0; col < 64; col++) {
        if (tid < 64) {
            double v = (tid >= col) ? fabs(g_aug[tid * 128 + col]) : -1.0;
            int r = tid;
            for (int off = 16; off; off >>= 1) {
                double ov = __shfl_down_sync(0xffffffffu, v, off);
                int orr = __shfl_down_sync(0xffffffffu, r, off);
                if (ov > v) { v = ov; r = orr; }
            }
            if ((tid & 31) == 0) { s_bv[tid >> 5] = v; s_br[tid >> 5] = r; }
        }
        __syncthreads();
        if (tid == 0) s_piv = (s_bv[1] > s_bv[0]) ? s_br[1] : s_br[0];
        __syncthreads();
        int piv = s_piv;
        int ncol = 128 - col;
        if (piv != col && tid < ncol) {
            int c = col + tid;
            double t = g_aug[piv * 128 + c];
            g_aug[piv * 128 + c] = g_aug[col * 128 + c];
            g_aug[col * 128 + c] = t;
        }
        __syncthreads();
        if (tid == 0) s_pv = g_aug[col * 128 + col];
        __syncthreads();
        if (tid < ncol) g_aug[col * 128 + col + tid] /= s_pv;
        __syncthreads();
        if (tid < 64) s_f[tid] = (tid == col) ? 0.0 : g_aug[tid * 128 + col];
        __syncthreads();
        int total = 64 * ncol;
        for (int t = tid; t < total; t += 256) {
            int r = t / ncol, c = col + (t - r * ncol);
            g_aug[r * 128 + c] -= s_f[r] * g_aug[col * 128 + c];
        }
        __syncthreads();
    }
    for (int idx = tid; idx < 4096; idx += 256)
        g_Finv[idx] = (float)g_aug[(idx >> 6) * 128 + 64 + (idx & 63)];
    // tail fold: Wf = proj_w^T @ obj_emb @ m_eff @ out_w^T
    if (tid == 0) {
        float m = functor_w[0];
        for (int i = 1; i < 64; i++) m = fmaxf(m, functor_w[i]);
        float s = 0.f;
        for (int i = 0; i < 64; i++) { float e = expf(functor_w[i] - m); s_fw[i] = e; s += e; }
        for (int i = 0; i < 64; i++) s_fw[i] /= s;
    }
    __syncthreads();
    for (int idx = tid; idx < 4096; idx += 256) {  // m_eff
        float s = 0.f;
        for (int m = 0; m < 64; m++) s += s_fw[m] * morphisms[m * 4096 + idx];
        s_a[idx] = s;
    }
    __syncthreads();
    for (int idx = tid; idx < 4096; idx += 256) {  // A2 = obj_emb @ m_eff
        int k = idx >> 6, j = idx & 63;
        float s = 0.f;
        for (int i = 0; i < 64; i++) s += obj_emb[k * 64 + i] * s_a[i * 64 + j];
        s_b[idx] = s;
    }
    __syncthreads();
    for (int idx = tid; idx < 4096; idx += 256) {  // A3 = A2 @ out_w^T
        int k = idx >> 6, o = idx & 63;
        float s = 0.f;
        for (int j = 0; j < 64; j++) s += s_b[k * 64 + j] * out_w[o * 64 + j];
        s_a[idx] = s;
    }
    __syncthreads();
    for (int idx = tid; idx < 4096; idx += 256) {  // Wf = proj_w^T @ A3
        int t = idx >> 6, o = idx & 63;
        float s = 0.f;
        for (int k = 0; k < 64; k++) s += proj_w[k * 64 + t] * s_a[k * 64 + o];
        g_Wf[idx] = s;
    }
    if (tid < 64) {
        float s = out_b[tid];
        for (int k = 0; k < 64; k++) s += proj_b[k] * s_a[k * 64 + tid];
        g_bf[tid] = s;
    }
}

// ============ K0b: Dsym[p][o] = sum_k (C[i,j,k]+C[j,i,k]) * Wf[k][o] ============
__global__ void k0b(const float* __restrict__ conn) {
    __shared__ float Wsh[4096];
    int tid = threadIdx.x;
    for (int idx = tid; idx < 4096; idx += 256) Wsh[idx] = g_Wf[idx];
    __syncthreads();
    int idx = blockIdx.x * 256 + tid;
    int p = idx >> 6, o = idx & 63;
    int i = 0, rem = p;
    while (rem >= 64 - i) { rem -= 64 - i; i++; }
    int j = i + rem;
    const float* c1 = conn + (i * 64 + j) * 64;
    const float* c2 = conn + (j * 64 + i) * 64;
    float s = 0.f;
    if (i == j) { for (int k = 0; k < 64; k++) s += c1[k] * Wsh[k * 64 + o]; }
    else { for (int k = 0; k < 64; k++) s += (c1[k] + c2[k]) * Wsh[k * 64 + o]; }
    g_Dsym[idx] = s;
}

// ============ K0c: KT[jd][o] = tk[o][jd] ============
__global__ void k0c(const float* __restrict__ tk) {
    int idx = blockIdx.x * 256 + threadIdx.x;
    int jd = idx >> 6, o = idx & 63;
    g_KT[jd * 64 + o] = tk[o * 768 + jd];
}

// ============ K1: topo (tile 256, 2 elems/thread) ============
__global__ void __launch_bounds__(256, 2) k_topo(const float* __restrict__ pers) {
    extern __shared__ float buf[];  // 6144 floats (32 j = 96 rows)
    int tid = threadIdx.x, lt = tid & 127, ob = (tid >> 7) * 32;
    int b = blockIdx.x * 256 + lt;
    u64 a1[16], a2[16];
#pragma unroll
    for (int q = 0; q < 16; q++) { a1[q] = 0ull; a2[q] = 0ull; }
    for (int c = 0; c < 8; c++) {
        STAGE(buf, g_KT + c * 6144, 1536);
#pragma unroll 2
        for (int jj = 0; jj < 32; jj++) {
            int j = c * 32 + jj;
            size_t base = ((size_t)j * Bn + b) * 6;
            float2 p0 = __ldcs((const float2*)(pers + base));
            float2 p1 = __ldcs((const float2*)(pers + base + 2));
            float2 p2 = __ldcs((const float2*)(pers + base + 4));
            float2 q0 = __ldcs((const float2*)(pers + base + 768));
            float2 q1 = __ldcs((const float2*)(pers + base + 770));
            float2 q2 = __ldcs((const float2*)(pers + base + 772));
            float sd1[3] = {p0.x + p0.y, p1.x + p1.y, p2.x + p2.y};
            float sd2[3] = {q0.x + q0.y, q1.x + q1.y, q2.x + q2.y};
#pragma unroll
            for (int d = 0; d < 3; d++) {
                u64 v1 = pk2(sd1[d], sd1[d]);
                u64 v2 = pk2(sd2[d], sd2[d]);
                const ulonglong2* row = (const ulonglong2*)(buf + (jj * 3 + d) * 64 + ob);
#pragma unroll
                for (int q = 0; q < 8; q++) {
                    ulonglong2 w = row[q];
                    a1[2 * q] = ffma2(v1, w.x, a1[2 * q]);
                    a1[2 * q + 1] = ffma2(v1, w.y, a1[2 * q + 1]);
                    a2[2 * q] = ffma2(v2, w.x, a2[2 * q]);
                    a2[2 * q + 1] = ffma2(v2, w.y, a2[2 * q + 1]);
                }
            }
        }
    }
#pragma unroll
    for (int q = 0; q < 16; q++) {
        float lo, hi;
        upk2(a1[q], lo, hi);
        g_topo[(ob + 2 * q) * Bn + b] = lo;
        g_topo[(ob + 2 * q + 1) * Bn + b] = hi;
        upk2(a2[q], lo, hi);
        g_topo[(ob + 2 * q) * Bn + b + 128] = lo;
        g_topo[(ob + 2 * q + 1) * Bn + b + 128] = hi;
    }
}

// ============ K2: q/k/v (tile 256, 2 elems/thread) ============
__global__ void __launch_bounds__(256, 2) k_qkv(const float* __restrict__ qb,
                                                const float* __restrict__ kb,
                                                const float* __restrict__ vb) {
    extern __shared__ float sm[];
    float* in_sh = sm;           // 16384
    float* buf = sm + 16384;     // 4096
    __shared__ float bsh[192];
    int tid = threadIdx.x, lt = tid & 127, ob = (tid >> 7) * 32;
    int b0 = blockIdx.x * 256, b = b0 + lt;
    if (tid < 64) { bsh[tid] = qb[tid]; bsh[64 + tid] = kb[tid]; bsh[128 + tid] = vb[tid]; }
    for (int idx = tid; idx < 16384; idx += 256)
        in_sh[idx] = g_topo[(idx >> 8) * Bn + b0 + (idx & 255)];
    const float* Wg[3] = {g_WqT, g_WkT, g_WvT};
    float* outg[3] = {g_qv, g_kv, g_vv};
    for (int s = 0; s < 3; s++) {
        STAGE(buf, Wg[s], 1024);
        u64 a1[16], a2[16];
#pragma unroll
        for (int q = 0; q < 16; q++) { a1[q] = 0ull; a2[q] = 0ull; }
        gemv32x2(in_sh, buf, lt, ob, a1, a2);
#pragma unroll
        for (int q = 0; q < 16; q++) {
            float lo, hi;
            float b1 = bsh[s * 64 + ob + 2 * q], b2 = bsh[s * 64 + ob + 2 * q + 1];
            upk2(a1[q], lo, hi);
            outg[s][(ob + 2 * q) * Bn + b] = lo + b1;
            outg[s][(ob + 2 * q + 1) * Bn + b] = hi + b2;
            upk2(a2[q], lo, hi);
            outg[s][(ob + 2 * q) * Bn + b + 128] = lo + b1;
            outg[s][(ob + 2 * q + 1) * Bn + b + 128] = hi + b2;
        }
    }
}

// ============ K3: attention + o-proj (tile 128) ============
__global__ void __launch_bounds__(256, 2) k_att(const float* __restrict__ ob_bias) {
    extern __shared__ float sm[];
    float* k_sh = sm;            // 8192
    float* v_sh = sm + 8192;     // 8192
    float* buf = sm + 16384;     // 4096 (WoT)
    __shared__ float cos_sh[64], obb[64];
    int tid = threadIdx.x, lt = tid & 127, ob = (tid >> 7) * 32;
    int b0 = blockIdx.x * 128, b = b0 + lt;
    if (tid < 64) { cos_sh[tid] = g_cosd[tid]; obb[tid] = ob_bias[tid]; }
    for (int idx = tid; idx < 8192; idx += 256) {
        int i = idx >> 7, c = idx & 127;
        k_sh[idx] = g_kv[i * Bn + b0 + c];
        v_sh[idx] = g_vv[i * Bn + b0 + c];
    }
    STAGE(buf, g_WoT, 1024);
    u64 acc[16];
#pragma unroll
    for (int q = 0; q < 16; q++) acc[q] = 0ull;
    for (int h = 0; h < 8; h++) {
        float qh[8];
#pragma unroll
        for (int d = 0; d < 8; d++) qh[d] = g_qv[(h * 8 + d) * Bn + b];
        float s[8];
#pragma unroll
        for (int g = 0; g < 8; g++) {
            float dot = 0.f;
#pragma unroll
            for (int d = 0; d < 8; d++) dot += qh[d] * k_sh[(g * 8 + d) * 128 + lt];
            s[g] = dot * cos_sh[h * 8 + g] * 0.35355339059327373f;
        }
        float m = s[0];
#pragma unroll
        for (int g = 1; g < 8; g++) m = fmaxf(m, s[g]);
        float sum = 0.f;
#pragma unroll
        for (int g = 0; g < 8; g++) { s[g] = expf(s[g] - m); sum += s[g]; }
        float inv = 1.0f / sum;
        float av8[8] = {0, 0, 0, 0, 0, 0, 0, 0};
#pragma unroll
        for (int g = 0; g < 8; g++) {
            float w = s[g] * inv;
#pragma unroll
            for (int d = 0; d < 8; d++) av8[d] += w * v_sh[(g * 8 + d) * 128 + lt];
        }
#pragma unroll
        for (int d = 0; d < 8; d++) {
            u64 xv = pk2(av8[d], av8[d]);
            const ulonglong2* row = (const ulonglong2*)(buf + (h * 8 + d) * 64 + ob);
#pragma unroll
            for (int q = 0; q < 8; q++) {
                ulonglong2 w = row[q];
                acc[2 * q] = ffma2(xv, w.x, acc[2 * q]);
                acc[2 * q + 1] = ffma2(xv, w.y, acc[2 * q + 1]);
            }
        }
    }
#pragma unroll
    for (int q = 0; q < 16; q++) {
        float lo, hi; upk2(acc[q], lo, hi);
        g_quant[(ob + 2 * q) * Bn + b] = lo + obb[ob + 2 * q];
        g_quant[(ob + 2 * q + 1) * Bn + b] = hi + obb[ob + 2 * q + 1];
    }
}

// ============ K4: update+cand+Finv+metric fused (tile 128) ============
__global__ void __launch_bounds__(256, 2) k_ucx(const float* __restrict__ ub,
                                                const float* __restrict__ sb) {
    extern __shared__ float sm[];
    float* in_sh = sm;          // 8192
    float* c_sh = sm + 8192;    // 8192
    float* buf = sm + 16384;    // 4096
    __shared__ float bsh[128];
    int tid = threadIdx.x, lt = tid & 127, ob = (tid >> 7) * 32;
    int b0 = blockIdx.x * 128, b = b0 + lt;
    if (tid < 64) { bsh[tid] = ub[tid]; bsh[64 + tid] = sb[tid]; }
    for (int idx = tid; idx < 8192; idx += 256)
        in_sh[idx] = g_quant[(idx >> 7) * Bn + b0 + (idx & 127)];
    // update gate
    STAGE(buf, g_WuT, 1024);
    u64 acc[16];
#pragma unroll
    for (int q = 0; q < 16; q++) acc[q] = 0ull;
    gemv32(in_sh, buf, lt, ob, acc);
    float ur[32];
#pragma unroll
    for (int q = 0; q < 16; q++) {
        float lo, hi; upk2(acc[q], lo, hi);
        ur[2 * q] = 1.0f / (1.0f + expf(-(lo + bsh[ob + 2 * q])));
        ur[2 * q + 1] = 1.0f / (1.0f + expf(-(hi + bsh[ob + 2 * q + 1])));
    }
    // candidate
    STAGE(buf, g_WsT, 1024);
#pragma unroll
    for (int q = 0; q < 16; q++) acc[q] = 0ull;
    gemv32(in_sh, buf, lt, ob, acc);
#pragma unroll
    for (int q = 0; q < 16; q++) {
        float lo, hi; upk2(acc[q], lo, hi);
        c_sh[(ob + 2 * q) * 128 + lt] = tanhf(lo + bsh[64 + ob + 2 * q]);
        c_sh[(ob + 2 * q + 1) * 128 + lt] = tanhf(hi + bsh[64 + ob + 2 * q + 1]);
    }
    // h = u * (Finv @ cand)
    STAGE(buf, g_Finv, 1024);
#pragma unroll
    for (int q = 0; q < 16; q++) acc[q] = 0ull;
    gemv32(c_sh, buf, lt, ob, acc);
#pragma unroll
    for (int q = 0; q < 16; q++) {
        float lo, hi; upk2(acc[q], lo, hi);
        in_sh[(ob + 2 * q) * 128 + lt] = lo * ur[2 * q];
        in_sh[(ob + 2 * q + 1) * 128 + lt] = hi * ur[2 * q + 1];
    }
    // xm = h @ metric
    STAGE(buf, g_metric, 1024);
#pragma unroll
    for (int q = 0; q < 16; q++) acc[q] = 0ull;
    gemv32(in_sh, buf, lt, ob, acc);
#pragma unroll
    for (int q = 0; q < 16; q++) {
        float lo, hi; upk2(acc[q], lo, hi);
        g_xm[(ob + 2 * q) * Bn + b] = lo;
        g_xm[(ob + 2 * q + 1) * Bn + b] = hi;
    }
}

// ============ K5: bilinear + tail (tile 256, 2 elems/thread) ============
__global__ void __launch_bounds__(256, 2) k_bil(float* __restrict__ out) {
    extern __shared__ float sm[];
    float* in_sh = sm;          // 16384
    float* buf = sm + 16384;    // 4096
    __shared__ float bf_sh[64];
    int tid = threadIdx.x, lt = tid & 127, ob = (tid >> 7) * 32;
    int b0 = blockIdx.x * 256, b = b0 + lt;
    if (tid < 64) bf_sh[tid] = g_bf[tid];
    for (int idx = tid; idx < 16384; idx += 256)
        in_sh[idx] = g_xm[(idx >> 8) * Bn + b0 + (idx & 255)];
    STAGE(buf, g_Wf, 1024);
    u64 a1[16], a2[16];
#pragma unroll
    for (int q = 0; q < 16; q++) { a1[q] = 0ull; a2[q] = 0ull; }
    gemv32x2(in_sh, buf, lt, ob, a1, a2);
    int pi = 0, pj = 0;
    float xi1 = in_sh[lt], xi2 = in_sh[128 + lt];
    for (int c0 = 0; c0 < NP; c0 += 64) {
        int nch = min(64, NP - c0);
        STAGE(buf, g_Dsym + c0 * 64, nch * 16);
        for (int p = 0; p < nch; p++) {
            float pr1 = xi1 * in_sh[pj * 256 + lt];
            float pr2 = xi2 * in_sh[pj * 256 + 128 + lt];
            u64 v1 = pk2(pr1, pr1), v2 = pk2(pr2, pr2);
            const ulonglong2* row = (const ulonglong2*)(buf + p * 64 + ob);
#pragma unroll
            for (int q = 0; q < 8; q++) {
                ulonglong2 w = row[q];
                a1[2 * q] = ffma2(v1, w.x, a1[2 * q]);
                a1[2 * q + 1] = ffma2(v1, w.y, a1[2 * q + 1]);
                a2[2 * q] = ffma2(v2, w.x, a2[2 * q]);
                a2[2 * q + 1] = ffma2(v2, w.y, a2[2 * q + 1]);
            }
            pj++;
            if (pj == 64) {
                pi++; pj = pi;
                xi1 = in_sh[pi * 256 + lt];
                xi2 = in_sh[pi * 256 + 128 + lt];
            }
        }
    }
    float4* o1 = (float4*)(out + (size_t)b * 64 + ob);
    float4* o2 = (float4*)(out + (size_t)(b + 128) * 64 + ob);
#pragma unroll
    for (int q = 0; q < 8; q++) {
        float c0f = bf_sh[ob + 4 * q], c1f = bf_sh[ob + 4 * q + 1];
        float c2f = bf_sh[ob + 4 * q + 2], c3f = bf_sh[ob + 4 * q + 3];
        float x0, x1, x2, x3;
        upk2(a1[2 * q], x0, x1); upk2(a1[2 * q + 1], x2, x3);
        o1[q] = make_float4(x0 + c0f, x1 + c1f, x2 + c2f, x3 + c3f);
        upk2(a2[2 * q], x0, x1); upk2(a2[2 * q + 1], x2, x3);
        o2[q] = make_float4(x0 + c0f, x1 + c1f, x2 + c2f, x3 + c3f);
    }
}

extern "C" void kernel_launch(void* const* d_in, const int* in_sizes, int n_in,
                              void* d_out, int out_size) {
    const float* pers     = (const float*)d_in[1];
    const float* tk       = (const float*)d_in[2];
    const float* q_w = (const float*)d_in[3],  *q_b = (const float*)d_in[4];
    const float* k_w = (const float*)d_in[5],  *k_b = (const float*)d_in[6];
    const float* v_w = (const float*)d_in[7],  *v_b = (const float*)d_in[8];
    const float* o_w = (const float*)d_in[9],  *o_b = (const float*)d_in[10];
    const float* phase = (const float*)d_in[11];
    const float* update_w = (const float*)d_in[12], *update_b = (const float*)d_in[13];
    const float* state_w  = (const float*)d_in[16], *state_b  = (const float*)d_in[17];
    const float* fisher_m = (const float*)d_in[18];
    const float* metric_m = (const float*)d_in[19];
    const float* connection = (const float*)d_in[20];
    const float* proj_w = (const float*)d_in[21], *proj_b = (const float*)d_in[22];
    const float* obj_emb = (const float*)d_in[23];
    const float* morphisms = (const float*)d_in[24];
    const float* functor_w = (const float*)d_in[25];
    const float* out_w = (const float*)d_in[26], *out_b = (const float*)d_in[27];
    float* out = (float*)d_out;

    static bool inited = false;
    static cudaStream_t s2;
    static cudaEvent_t ev1, ev2;
    if (!inited) {
        cudaFuncSetAttribute(k_topo, cudaFuncAttributeMaxDynamicSharedMemorySize, 6144 * 4);
        cudaFuncSetAttribute(k_qkv, cudaFuncAttributeMaxDynamicSharedMemorySize, 20480 * 4);
        cudaFuncSetAttribute(k_att, cudaFuncAttributeMaxDynamicSharedMemorySize, 20480 * 4);
        cudaFuncSetAttribute(k_ucx, cudaFuncAttributeMaxDynamicSharedMemorySize, 20480 * 4);
        cudaFuncSetAttribute(k_bil, cudaFuncAttributeMaxDynamicSharedMemorySize, 20480 * 4);
        cudaStreamCreateWithFlags(&s2, cudaStreamNonBlocking);
        cudaEventCreateWithFlags(&ev1, cudaEventDisableTiming);
        cudaEventCreateWithFlags(&ev2, cudaEventDisableTiming);
        inited = true;
    }
    // fork: precompute (k0a,k0b) runs under k_topo
    cudaEventRecord(ev1, 0);
    cudaStreamWaitEvent(s2, ev1, 0);
    k0a<<<1, 256, 0, s2>>>(phase, q_w, k_w, v_w, o_w, update_w, state_w, fisher_m,
                           metric_m, proj_w, proj_b, obj_emb, morphisms, functor_w,
                           out_w, out_b);
    k0b<<<NP * 64 / 256, 256, 0, s2>>>(connection);
    cudaEventRecord(ev2, s2);
    k0c<<<768 * 64 / 256, 256>>>(tk);
    k_topo<<<Bn / 256, 256, 6144 * 4>>>(pers);
    cudaStreamWaitEvent(0, ev2, 0);  // join before weights are needed
    k_qkv<<<Bn / 256, 256, 20480 * 4>>>(q_b, k_b, v_b);
    k_att<<<Bn / 128, 256, 20480 * 4>>>(o_b);
    k_ucx<<<Bn / 128, 256, 20480 * 4>>>(update_b, state_b);
    k_bil<<<Bn / 256, 256, 20480 * 4>>>(out);
}